// round 12
// baseline (speedup 1.0000x reference)
#include <cuda_runtime.h>
#include <cuda_bf16.h>

// ---------------------------------------------------------------------------
// 3-layer weighted GCN:
//   nw  = w / sqrt(max(outdeg_w[src] * indeg_w[dst], EPS))      (EdgeWeightNorm 'both')
//   h   = x @ W                                                  (transform first)
//   agg[dst] += nw * h[src]                                      (edge scatter, vector RED)
//   out = agg / max(sum(nw by dst), EPS) + b                     (GraphConv 'right')
// ---------------------------------------------------------------------------

#define NN 100000
#define EE 1600000
#define F_IN  128
#define F_HID 64
#define F_OUT 32

static __device__ float g_nw[EE];
static __device__ float g_degbuf[3 * NN];     // [outdeg | indeg | deg]
static __device__ float g_h[NN * F_HID];      // transformed features (max 64 wide)
static __device__ float g_agg[NN * F_HID];    // aggregation accumulator
static __device__ float g_o1[NN * F_HID];     // layer-1 output
static __device__ float g_o2[NN * F_OUT];     // layer-2 output

__device__ __forceinline__ float gcn_eps() { return 1e-12f; }

// ---------------- zero (float4) ----------------
__global__ void zero4_kernel(float4* __restrict__ p, int n4) {
    int i = blockIdx.x * blockDim.x + threadIdx.x;
    if (i < n4) p[i] = make_float4(0.f, 0.f, 0.f, 0.f);
}

// ---------------- weighted degree histograms ----------------
__global__ void deg_kernel(const int* __restrict__ src, const int* __restrict__ dst,
                           const float* __restrict__ w,
                           float* __restrict__ outdeg, float* __restrict__ indeg, int e) {
    int i = blockIdx.x * blockDim.x + threadIdx.x;
    if (i >= e) return;
    float ww = w[i];
    atomicAdd(&outdeg[src[i]], ww);
    atomicAdd(&indeg[dst[i]], ww);
}

// ---------------- edge norm + right-norm denominator ----------------
__global__ void nw_kernel(const int* __restrict__ src, const int* __restrict__ dst,
                          const float* __restrict__ w,
                          const float* __restrict__ outdeg, const float* __restrict__ indeg,
                          float* __restrict__ nw, float* __restrict__ deg, int e) {
    int i = blockIdx.x * blockDim.x + threadIdx.x;
    if (i >= e) return;
    int s = src[i], d = dst[i];
    float p = outdeg[s] * indeg[d];
    float v = w[i] * rsqrtf(fmaxf(p, gcn_eps()));
    nw[i] = v;
    atomicAdd(&deg[d], v);
}

// ---------------- dense GEMM: out[n, FOUT] = x[n, FIN] @ W[FIN, FOUT] ----------------
template <int FIN, int FOUT>
__global__ void gemm_kernel(const float* __restrict__ x, const float* __restrict__ Wg,
                            float* __restrict__ out, int n) {
    constexpr int TM  = 16;             // rows per block
    constexpr int TPR = 16;             // threads per row (blockDim = 256)
    constexpr int CPT = FOUT / TPR;     // cols per thread (4 or 2)
    constexpr int XSS = FIN + 4;        // padded row stride (bank-conflict free, 16B aligned)
    __shared__ float Ws[FIN * FOUT];
    __shared__ float Xs[TM * XSS];

    int tid = threadIdx.x;
    for (int i = tid; i < FIN * FOUT / 4; i += 256)
        ((float4*)Ws)[i] = ((const float4*)Wg)[i];

    int row0 = blockIdx.x * TM;
    constexpr int XC = FIN / 4;
    for (int i = tid; i < TM * XC; i += 256) {
        int r = i / XC, c = i - r * XC;
        float4 v = make_float4(0.f, 0.f, 0.f, 0.f);
        if (row0 + r < n)
            v = ((const float4*)(x + (size_t)(row0 + r) * FIN))[c];
        ((float4*)(Xs + r * XSS))[c] = v;
    }
    __syncthreads();

    int r  = tid / TPR;
    int c0 = (tid - r * TPR) * CPT;
    float acc[CPT];
#pragma unroll
    for (int j = 0; j < CPT; ++j) acc[j] = 0.f;

#pragma unroll
    for (int k = 0; k < FIN; ++k) {
        float xv = Xs[r * XSS + k];
#pragma unroll
        for (int j = 0; j < CPT; ++j)
            acc[j] = fmaf(xv, Ws[k * FOUT + c0 + j], acc[j]);
    }

    int row = row0 + r;
    if (row < n) {
#pragma unroll
        for (int j = 0; j < CPT; ++j)
            out[(size_t)row * FOUT + c0 + j] = acc[j];
    }
}

// ---------------- edge scatter: agg[dst] += nw * h[src] (vector RED) ----------------
// TPE = FOUT/4 threads per edge, each handles one float4 chunk of the feature row.
template <int TPE>
__global__ void scatter_kernel(const int* __restrict__ src, const int* __restrict__ dst,
                               const float* __restrict__ nw, const float* __restrict__ h,
                               float* __restrict__ agg, int e) {
    int gid  = blockIdx.x * blockDim.x + threadIdx.x;
    int edge = gid / TPE;
    int lane = gid - edge * TPE;
    if (edge >= e) return;
    int   s = src[edge];
    int   d = dst[edge];
    float c = nw[edge];
    float4 hv = ((const float4*)h)[(size_t)s * TPE + lane];
    float* addr = agg + ((size_t)d * TPE + lane) * 4;
    asm volatile("red.global.add.v4.f32 [%0], {%1,%2,%3,%4};"
                 :: "l"(__cvta_generic_to_global(addr)),
                    "f"(hv.x * c), "f"(hv.y * c), "f"(hv.z * c), "f"(hv.w * c)
                 : "memory");
}

// ---------------- finalize: out = agg / max(deg, EPS) + b ----------------
template <int FOUT>
__global__ void finalize_kernel(const float* __restrict__ agg, const float* __restrict__ deg,
                                const float* __restrict__ b, float* __restrict__ out, int n) {
    constexpr int C4 = FOUT / 4;
    int idx = blockIdx.x * blockDim.x + threadIdx.x;
    if (idx >= n * C4) return;
    int node = idx / C4;
    int c    = idx - node * C4;
    float dv = fmaxf(deg[node], gcn_eps());
    float4 a  = ((const float4*)agg)[idx];
    float4 bb = ((const float4*)b)[c];
    float4 o;
    o.x = a.x / dv + bb.x;
    o.y = a.y / dv + bb.y;
    o.z = a.z / dv + bb.z;
    o.w = a.w / dv + bb.w;
    ((float4*)out)[idx] = o;
}

// ---------------------------------------------------------------------------

static inline int nblk(long long t, int tb) { return (int)((t + tb - 1) / tb); }

template <int FIN, int FOUT>
static void run_layer(const float* x_in, const int* src, const int* dst, const float* w,
                      const float* W, const float* b, float* out,
                      float* nw, float* degbuf, float* h, float* agg, int n, int e) {
    float* outdeg = degbuf;
    float* indeg  = degbuf + NN;
    float* deg    = degbuf + 2 * NN;
    const int TB = 256;

    zero4_kernel<<<nblk((3 * NN) / 4, TB), TB>>>((float4*)degbuf, (3 * NN) / 4);
    deg_kernel<<<nblk(e, TB), TB>>>(src, dst, w, outdeg, indeg, e);
    nw_kernel<<<nblk(e, TB), TB>>>(src, dst, w, outdeg, indeg, nw, deg, e);
    gemm_kernel<FIN, FOUT><<<nblk(n, 16), TB>>>(x_in, W, h, n);
    zero4_kernel<<<nblk((long long)n * FOUT / 4, TB), TB>>>((float4*)agg, n * FOUT / 4);
    constexpr int TPE = FOUT / 4;
    scatter_kernel<TPE><<<nblk((long long)e * TPE, TB), TB>>>(src, dst, nw, h, agg, e);
    finalize_kernel<FOUT><<<nblk((long long)n * FOUT / 4, TB), TB>>>(agg, deg, b, out, n);
}

extern "C" void kernel_launch(void* const* d_in, const int* in_sizes, int n_in,
                              void* d_out, int out_size) {
    const float* x    = (const float*)d_in[0];
    const int*   src1 = (const int*)d_in[1];
    const int*   dst1 = (const int*)d_in[2];
    const float* w1   = (const float*)d_in[3];
    const int*   src2 = (const int*)d_in[4];
    const int*   dst2 = (const int*)d_in[5];
    const float* w2   = (const float*)d_in[6];
    const int*   src3 = (const int*)d_in[7];
    const int*   dst3 = (const int*)d_in[8];
    const float* w3   = (const float*)d_in[9];
    const float* W1   = (const float*)d_in[10];
    const float* b1   = (const float*)d_in[11];
    const float* W2   = (const float*)d_in[12];
    const float* b2   = (const float*)d_in[13];
    const float* W3   = (const float*)d_in[14];
    const float* b3   = (const float*)d_in[15];

    int n  = in_sizes[0] / F_IN;     // 100000
    int e1 = in_sizes[1];
    int e2 = in_sizes[4];
    int e3 = in_sizes[7];

    float *nw, *degbuf, *h, *agg, *o1, *o2;
    cudaGetSymbolAddress((void**)&nw,     g_nw);
    cudaGetSymbolAddress((void**)&degbuf, g_degbuf);
    cudaGetSymbolAddress((void**)&h,      g_h);
    cudaGetSymbolAddress((void**)&agg,    g_agg);
    cudaGetSymbolAddress((void**)&o1,     g_o1);
    cudaGetSymbolAddress((void**)&o2,     g_o2);

    float* out = (float*)d_out;

    run_layer<F_IN,  F_HID>(x,  src1, dst1, w1, W1, b1, o1,  nw, degbuf, h, agg, n, e1);
    run_layer<F_HID, F_OUT>(o1, src2, dst2, w2, W2, b2, o2,  nw, degbuf, h, agg, n, e2);
    run_layer<F_OUT, F_OUT>(o2, src3, dst3, w3, W3, b3, out, nw, degbuf, h, agg, n, e3);
}

// round 14
// speedup vs baseline: 1.8660x; 1.8660x over previous
#include <cuda_runtime.h>
#include <cuda_bf16.h>

// ---------------------------------------------------------------------------
// 3-layer weighted GCN:
//   nw  = w / sqrt(max(outdeg_w[src] * indeg_w[dst], EPS))      (EdgeWeightNorm 'both')
//   h   = x @ W                                                  (transform first)
//   agg[dst] += nw * h[src]                                      (edge scatter, vector RED)
//   out = agg / max(sum(nw by dst), EPS) + b                     (GraphConv 'right')
// ---------------------------------------------------------------------------

#define NN 100000
#define EE 1600000
#define F_IN  128
#define F_HID 64
#define F_OUT 32

static __device__ float g_nw[EE];
static __device__ float g_degbuf[3 * NN];     // [outdeg | indeg | deg]
static __device__ float g_h[NN * F_HID];      // transformed features (max 64 wide)
static __device__ float g_agg[NN * F_HID];    // aggregation accumulator
static __device__ float g_o1[NN * F_HID];     // layer-1 output
static __device__ float g_o2[NN * F_OUT];     // layer-2 output

__device__ __forceinline__ float gcn_eps() { return 1e-12f; }

// ---------------- zero (float4) ----------------
__global__ void zero4_kernel(float4* __restrict__ p, int n4) {
    int i = blockIdx.x * blockDim.x + threadIdx.x;
    if (i < n4) p[i] = make_float4(0.f, 0.f, 0.f, 0.f);
}

// ---------------- weighted degree histograms ----------------
__global__ void deg_kernel(const int* __restrict__ src, const int* __restrict__ dst,
                           const float* __restrict__ w,
                           float* __restrict__ outdeg, float* __restrict__ indeg, int e) {
    int i = blockIdx.x * blockDim.x + threadIdx.x;
    if (i >= e) return;
    float ww = w[i];
    atomicAdd(&outdeg[src[i]], ww);
    atomicAdd(&indeg[dst[i]], ww);
}

// ---------------- edge norm + right-norm denominator ----------------
__global__ void nw_kernel(const int* __restrict__ src, const int* __restrict__ dst,
                          const float* __restrict__ w,
                          const float* __restrict__ outdeg, const float* __restrict__ indeg,
                          float* __restrict__ nw, float* __restrict__ deg, int e) {
    int i = blockIdx.x * blockDim.x + threadIdx.x;
    if (i >= e) return;
    int s = src[i], d = dst[i];
    float p = outdeg[s] * indeg[d];
    float v = w[i] * rsqrtf(fmaxf(p, gcn_eps()));
    nw[i] = v;
    atomicAdd(&deg[d], v);
}

// ---------------- register-tiled GEMM: out[n,FOUT] = x[n,FIN] @ W[FIN,FOUT] ----------
// Block: 128 rows x FOUT cols.  256 threads.  Thread tile: RPT rows x 4 cols.
// K chunked at KC=16 (smem Xs tile); whole W resident in smem.
// __launch_bounds__(256,3) caps regs at ~85 -> 3+ blocks/SM (fixes regs=255 blowup).
template <int FIN, int FOUT>
__global__ void __launch_bounds__(256, 3)
gemm_kernel(const float* __restrict__ x, const float* __restrict__ Wg,
            float* __restrict__ out, int n) {
    constexpr int TM     = 128;
    constexpr int KC     = 16;
    constexpr int KC_PAD = KC + 4;
    constexpr int TPR    = FOUT / 4;        // threads per row strip (16 or 8)
    constexpr int ROWG   = 256 / TPR;       // row groups (16 or 32)
    constexpr int RPT    = TM / ROWG;       // rows per thread (8 or 4)
    constexpr int QP     = KC / 4;          // float4s per row per chunk

    __shared__ float Ws[FIN * FOUT];
    __shared__ float Xs[TM][KC_PAD];

    const int tid = threadIdx.x;

    // whole W -> smem
    for (int i = tid; i < FIN * FOUT / 4; i += 256)
        ((float4*)Ws)[i] = ((const float4*)Wg)[i];

    const int row0 = blockIdx.x * TM;
    const int r0   = (tid / TPR) * RPT;
    const int c0   = (tid % TPR) * 4;

    float acc[RPT][4];
#pragma unroll
    for (int i = 0; i < RPT; ++i)
#pragma unroll
        for (int j = 0; j < 4; ++j) acc[i][j] = 0.f;

    for (int kc = 0; kc < FIN; kc += KC) {
        __syncthreads();   // protect Xs from previous chunk's readers
        // load Xs tile: TM rows x KC floats
#pragma unroll
        for (int i = tid; i < TM * QP; i += 256) {
            int r = i / QP, q = i - r * QP;
            float4 v = make_float4(0.f, 0.f, 0.f, 0.f);
            if (row0 + r < n)
                v = *(const float4*)(x + (size_t)(row0 + r) * FIN + kc + q * 4);
            *(float4*)&Xs[r][q * 4] = v;
        }
        __syncthreads();

#pragma unroll 8
        for (int k = 0; k < KC; ++k) {
            float4 wv = *(const float4*)&Ws[(kc + k) * FOUT + c0];
            float xv[RPT];
#pragma unroll
            for (int i = 0; i < RPT; ++i) xv[i] = Xs[r0 + i][k];
#pragma unroll
            for (int i = 0; i < RPT; ++i) {
                acc[i][0] = fmaf(xv[i], wv.x, acc[i][0]);
                acc[i][1] = fmaf(xv[i], wv.y, acc[i][1]);
                acc[i][2] = fmaf(xv[i], wv.z, acc[i][2]);
                acc[i][3] = fmaf(xv[i], wv.w, acc[i][3]);
            }
        }
    }

#pragma unroll
    for (int i = 0; i < RPT; ++i) {
        int row = row0 + r0 + i;
        if (row < n) {
            float4 o = make_float4(acc[i][0], acc[i][1], acc[i][2], acc[i][3]);
            *(float4*)(out + (size_t)row * FOUT + c0) = o;
        }
    }
}

// ---------------- edge scatter: agg[dst] += nw * h[src] (vector RED) ----------------
// TPE = FOUT/4 threads per edge, each handles one float4 chunk of the feature row.
template <int TPE>
__global__ void scatter_kernel(const int* __restrict__ src, const int* __restrict__ dst,
                               const float* __restrict__ nw, const float* __restrict__ h,
                               float* __restrict__ agg, int e) {
    int gid  = blockIdx.x * blockDim.x + threadIdx.x;
    int edge = gid / TPE;
    int lane = gid - edge * TPE;
    if (edge >= e) return;
    int   s = src[edge];
    int   d = dst[edge];
    float c = nw[edge];
    float4 hv = ((const float4*)h)[(size_t)s * TPE + lane];
    float* addr = agg + ((size_t)d * TPE + lane) * 4;
    asm volatile("red.global.add.v4.f32 [%0], {%1,%2,%3,%4};"
                 :: "l"(__cvta_generic_to_global(addr)),
                    "f"(hv.x * c), "f"(hv.y * c), "f"(hv.z * c), "f"(hv.w * c)
                 : "memory");
}

// ---------------- finalize: out = agg / max(deg, EPS) + b ----------------
template <int FOUT>
__global__ void finalize_kernel(const float* __restrict__ agg, const float* __restrict__ deg,
                                const float* __restrict__ b, float* __restrict__ out, int n) {
    constexpr int C4 = FOUT / 4;
    int idx = blockIdx.x * blockDim.x + threadIdx.x;
    if (idx >= n * C4) return;
    int node = idx / C4;
    int c    = idx - node * C4;
    float dv = fmaxf(deg[node], gcn_eps());
    float4 a  = ((const float4*)agg)[idx];
    float4 bb = ((const float4*)b)[c];
    float4 o;
    o.x = a.x / dv + bb.x;
    o.y = a.y / dv + bb.y;
    o.z = a.z / dv + bb.z;
    o.w = a.w / dv + bb.w;
    ((float4*)out)[idx] = o;
}

// ---------------------------------------------------------------------------

static inline int nblk(long long t, int tb) { return (int)((t + tb - 1) / tb); }

template <int FIN, int FOUT>
static void run_layer(const float* x_in, const int* src, const int* dst, const float* w,
                      const float* W, const float* b, float* out,
                      float* nw, float* degbuf, float* h, float* agg, int n, int e) {
    float* outdeg = degbuf;
    float* indeg  = degbuf + NN;
    float* deg    = degbuf + 2 * NN;
    const int TB = 256;

    zero4_kernel<<<nblk((3 * NN) / 4, TB), TB>>>((float4*)degbuf, (3 * NN) / 4);
    deg_kernel<<<nblk(e, TB), TB>>>(src, dst, w, outdeg, indeg, e);
    nw_kernel<<<nblk(e, TB), TB>>>(src, dst, w, outdeg, indeg, nw, deg, e);
    gemm_kernel<FIN, FOUT><<<nblk(n, 128), TB>>>(x_in, W, h, n);
    zero4_kernel<<<nblk((long long)n * FOUT / 4, TB), TB>>>((float4*)agg, n * FOUT / 4);
    constexpr int TPE = FOUT / 4;
    scatter_kernel<TPE><<<nblk((long long)e * TPE, TB), TB>>>(src, dst, nw, h, agg, e);
    finalize_kernel<FOUT><<<nblk((long long)n * FOUT / 4, TB), TB>>>(agg, deg, b, out, n);
}

extern "C" void kernel_launch(void* const* d_in, const int* in_sizes, int n_in,
                              void* d_out, int out_size) {
    const float* x    = (const float*)d_in[0];
    const int*   src1 = (const int*)d_in[1];
    const int*   dst1 = (const int*)d_in[2];
    const float* w1   = (const float*)d_in[3];
    const int*   src2 = (const int*)d_in[4];
    const int*   dst2 = (const int*)d_in[5];
    const float* w2   = (const float*)d_in[6];
    const int*   src3 = (const int*)d_in[7];
    const int*   dst3 = (const int*)d_in[8];
    const float* w3   = (const float*)d_in[9];
    const float* W1   = (const float*)d_in[10];
    const float* b1   = (const float*)d_in[11];
    const float* W2   = (const float*)d_in[12];
    const float* b2   = (const float*)d_in[13];
    const float* W3   = (const float*)d_in[14];
    const float* b3   = (const float*)d_in[15];

    int n  = in_sizes[0] / F_IN;     // 100000
    int e1 = in_sizes[1];
    int e2 = in_sizes[4];
    int e3 = in_sizes[7];

    float *nw, *degbuf, *h, *agg, *o1, *o2;
    cudaGetSymbolAddress((void**)&nw,     g_nw);
    cudaGetSymbolAddress((void**)&degbuf, g_degbuf);
    cudaGetSymbolAddress((void**)&h,      g_h);
    cudaGetSymbolAddress((void**)&agg,    g_agg);
    cudaGetSymbolAddress((void**)&o1,     g_o1);
    cudaGetSymbolAddress((void**)&o2,     g_o2);

    float* out = (float*)d_out;

    run_layer<F_IN,  F_HID>(x,  src1, dst1, w1, W1, b1, o1,  nw, degbuf, h, agg, n, e1);
    run_layer<F_HID, F_OUT>(o1, src2, dst2, w2, W2, b2, o2,  nw, degbuf, h, agg, n, e2);
    run_layer<F_OUT, F_OUT>(o2, src3, dst3, w3, W3, b3, out, nw, degbuf, h, agg, n, e3);
}

// round 15
// speedup vs baseline: 1.9045x; 1.0206x over previous
#include <cuda_runtime.h>
#include <cuda_bf16.h>

// ---------------------------------------------------------------------------
// 3-layer weighted GCN (DGL EdgeWeightNorm 'both' + GraphConv 'right')
// ---------------------------------------------------------------------------

#define NN 100000
#define EE 1600000
#define F_IN  128
#define F_HID 64
#define F_OUT 32

static __device__ float g_nw[3 * EE];         // per-layer normalized edge weights
static __device__ float g_degbuf[9 * NN];     // 3x [outdeg | indeg | deg]
static __device__ float g_h[NN * F_HID];      // transformed features
static __device__ float g_agg[NN * F_HID];    // aggregation accumulator
static __device__ float g_o1[NN * F_HID];
static __device__ float g_o2[NN * F_OUT];

__device__ __forceinline__ float gcn_eps() { return 1e-12f; }

// ---------------- zero (float4) ----------------
__global__ void zero4_kernel(float4* __restrict__ p, int n4) {
    int i = blockIdx.x * blockDim.x + threadIdx.x;
    if (i < n4) p[i] = make_float4(0.f, 0.f, 0.f, 0.f);
}

// ---------------- weighted degree histograms, all 3 layers in one launch -------------
__global__ void deg_all_kernel(const int* __restrict__ s1, const int* __restrict__ d1, const float* __restrict__ w1,
                               const int* __restrict__ s2, const int* __restrict__ d2, const float* __restrict__ w2,
                               const int* __restrict__ s3, const int* __restrict__ d3, const float* __restrict__ w3,
                               float* __restrict__ degbuf, int e1, int e2, int e3) {
    int i = blockIdx.x * blockDim.x + threadIdx.x;
    if (i >= e1 + e2 + e3) return;
    const int* src; const int* dst; const float* w; float* base; int j;
    if (i < e1)            { j = i;           src = s1; dst = d1; w = w1; base = degbuf; }
    else if (i < e1 + e2)  { j = i - e1;      src = s2; dst = d2; w = w2; base = degbuf + 3 * NN; }
    else                   { j = i - e1 - e2; src = s3; dst = d3; w = w3; base = degbuf + 6 * NN; }
    float ww = w[j];
    atomicAdd(&base[src[j]], ww);       // outdeg
    atomicAdd(&base[NN + dst[j]], ww);  // indeg
}

// ---------------- edge norm + right-norm denominator, all 3 layers -------------------
__global__ void nw_all_kernel(const int* __restrict__ s1, const int* __restrict__ d1, const float* __restrict__ w1,
                              const int* __restrict__ s2, const int* __restrict__ d2, const float* __restrict__ w2,
                              const int* __restrict__ s3, const int* __restrict__ d3, const float* __restrict__ w3,
                              const float* __restrict__ degbuf, float* __restrict__ nw,
                              float* __restrict__ degbuf_w, int e1, int e2, int e3) {
    int i = blockIdx.x * blockDim.x + threadIdx.x;
    if (i >= e1 + e2 + e3) return;
    const int* src; const int* dst; const float* w; const float* base; float* wbase; int j;
    if (i < e1)            { j = i;           src = s1; dst = d1; w = w1; base = degbuf;          wbase = degbuf_w; }
    else if (i < e1 + e2)  { j = i - e1;      src = s2; dst = d2; w = w2; base = degbuf + 3 * NN; wbase = degbuf_w + 3 * NN; }
    else                   { j = i - e1 - e2; src = s3; dst = d3; w = w3; base = degbuf + 6 * NN; wbase = degbuf_w + 6 * NN; }
    int s = src[j], d = dst[j];
    float p = base[s] * base[NN + d];                   // outdeg[s] * indeg[d]
    float v = w[j] * rsqrtf(fmaxf(p, gcn_eps()));
    nw[i] = v;
    atomicAdd(&wbase[2 * NN + d], v);                   // weighted in-degree of nw
}

// ---------------- register-tiled GEMM: out[n,FOUT] = x[n,FIN] @ W[FIN,FOUT] ----------
// 256 thr, 128-row tile, thread tile RPT x 4, transposed Xs (LDS.128 reads),
// launch_bounds(256,4) -> <=64 regs, 4 blocks/SM.
template <int FIN, int FOUT>
__global__ void __launch_bounds__(256, 4)
gemm_kernel(const float* __restrict__ x, const float* __restrict__ Wg,
            float* __restrict__ out, int n) {
    constexpr int TM   = 128;
    constexpr int KC   = 16;
    constexpr int TMP  = TM + 4;            // padded row length for XsT
    constexpr int TPR  = FOUT / 4;          // threads per row strip (16 or 8)
    constexpr int ROWG = 256 / TPR;         // row groups
    constexpr int RPT  = TM / ROWG;         // rows per thread (8 or 4)
    constexpr int R4   = RPT / 4;           // float4 chunks of rows (2 or 1)
    constexpr int QP   = KC / 4;

    __shared__ float Ws[FIN * FOUT];
    __shared__ float XsT[KC][TMP];          // transposed: [k][row]

    const int tid = threadIdx.x;

    for (int i = tid; i < FIN * FOUT / 4; i += 256)
        ((float4*)Ws)[i] = ((const float4*)Wg)[i];

    const int row0 = blockIdx.x * TM;
    const int r0   = (tid / TPR) * RPT;
    const int c0   = (tid % TPR) * 4;

    float acc[RPT][4];
#pragma unroll
    for (int i = 0; i < RPT; ++i)
#pragma unroll
        for (int j = 0; j < 4; ++j) acc[i][j] = 0.f;

    for (int kc = 0; kc < FIN; kc += KC) {
        __syncthreads();
#pragma unroll
        for (int i = tid; i < TM * QP; i += 256) {
            int r = i / QP, q = i - r * QP;
            float4 v = make_float4(0.f, 0.f, 0.f, 0.f);
            if (row0 + r < n)
                v = *(const float4*)(x + (size_t)(row0 + r) * FIN + kc + q * 4);
            XsT[q * 4 + 0][r] = v.x;
            XsT[q * 4 + 1][r] = v.y;
            XsT[q * 4 + 2][r] = v.z;
            XsT[q * 4 + 3][r] = v.w;
        }
        __syncthreads();

#pragma unroll
        for (int k = 0; k < KC; ++k) {
            float4 wv = *(const float4*)&Ws[(kc + k) * FOUT + c0];
            float4 xv4[R4];
#pragma unroll
            for (int u = 0; u < R4; ++u)
                xv4[u] = *(const float4*)&XsT[k][r0 + 4 * u];
            const float* xv = (const float*)xv4;
#pragma unroll
            for (int i = 0; i < RPT; ++i) {
                acc[i][0] = fmaf(xv[i], wv.x, acc[i][0]);
                acc[i][1] = fmaf(xv[i], wv.y, acc[i][1]);
                acc[i][2] = fmaf(xv[i], wv.z, acc[i][2]);
                acc[i][3] = fmaf(xv[i], wv.w, acc[i][3]);
            }
        }
    }

#pragma unroll
    for (int i = 0; i < RPT; ++i) {
        int row = row0 + r0 + i;
        if (row < n) {
            float4 o = make_float4(acc[i][0], acc[i][1], acc[i][2], acc[i][3]);
            *(float4*)(out + (size_t)row * FOUT + c0) = o;
        }
    }
}

// ---------------- edge scatter: agg[dst] += nw * h[src] (vector RED) ----------------
template <int TPE>
__global__ void scatter_kernel(const int* __restrict__ src, const int* __restrict__ dst,
                               const float* __restrict__ nw, const float* __restrict__ h,
                               float* __restrict__ agg, int e) {
    int gid  = blockIdx.x * blockDim.x + threadIdx.x;
    int edge = gid / TPE;
    int lane = gid - edge * TPE;
    if (edge >= e) return;
    int   s = src[edge];
    int   d = dst[edge];
    float c = nw[edge];
    float4 hv = ((const float4*)h)[(size_t)s * TPE + lane];
    float* addr = agg + ((size_t)d * TPE + lane) * 4;
    asm volatile("red.global.add.v4.f32 [%0], {%1,%2,%3,%4};"
                 :: "l"(__cvta_generic_to_global(addr)),
                    "f"(hv.x * c), "f"(hv.y * c), "f"(hv.z * c), "f"(hv.w * c)
                 : "memory");
}

// ---------------- finalize: out = agg / max(deg, EPS) + b ----------------
template <int FOUT>
__global__ void finalize_kernel(const float* __restrict__ agg, const float* __restrict__ deg,
                                const float* __restrict__ b, float* __restrict__ out, int n) {
    constexpr int C4 = FOUT / 4;
    int idx = blockIdx.x * blockDim.x + threadIdx.x;
    if (idx >= n * C4) return;
    int node = idx / C4;
    int c    = idx - node * C4;
    float dv = fmaxf(deg[node], gcn_eps());
    float4 a  = ((const float4*)agg)[idx];
    float4 bb = ((const float4*)b)[c];
    float4 o;
    o.x = a.x / dv + bb.x;
    o.y = a.y / dv + bb.y;
    o.z = a.z / dv + bb.z;
    o.w = a.w / dv + bb.w;
    ((float4*)out)[idx] = o;
}

// ---------------------------------------------------------------------------

static inline int nblk(long long t, int tb) { return (int)((t + tb - 1) / tb); }

template <int FIN, int FOUT>
static void run_layer(const float* x_in, const int* src, const int* dst,
                      const float* nw, const float* deg,
                      const float* W, const float* b, float* out,
                      float* h, float* agg, int n, int e) {
    const int TB = 256;
    gemm_kernel<FIN, FOUT><<<nblk(n, 128), TB>>>(x_in, W, h, n);
    zero4_kernel<<<nblk((long long)n * FOUT / 4, TB), TB>>>((float4*)agg, n * FOUT / 4);
    constexpr int TPE = FOUT / 4;
    scatter_kernel<TPE><<<nblk((long long)e * TPE, TB), TB>>>(src, dst, nw, h, agg, e);
    finalize_kernel<FOUT><<<nblk((long long)n * FOUT / 4, TB), TB>>>(agg, deg, b, out, n);
}

extern "C" void kernel_launch(void* const* d_in, const int* in_sizes, int n_in,
                              void* d_out, int out_size) {
    const float* x    = (const float*)d_in[0];
    const int*   src1 = (const int*)d_in[1];
    const int*   dst1 = (const int*)d_in[2];
    const float* w1   = (const float*)d_in[3];
    const int*   src2 = (const int*)d_in[4];
    const int*   dst2 = (const int*)d_in[5];
    const float* w2   = (const float*)d_in[6];
    const int*   src3 = (const int*)d_in[7];
    const int*   dst3 = (const int*)d_in[8];
    const float* w3   = (const float*)d_in[9];
    const float* W1   = (const float*)d_in[10];
    const float* b1   = (const float*)d_in[11];
    const float* W2   = (const float*)d_in[12];
    const float* b2   = (const float*)d_in[13];
    const float* W3   = (const float*)d_in[14];
    const float* b3   = (const float*)d_in[15];

    int n  = in_sizes[0] / F_IN;     // 100000
    int e1 = in_sizes[1];
    int e2 = in_sizes[4];
    int e3 = in_sizes[7];

    float *nw, *degbuf, *h, *agg, *o1, *o2;
    cudaGetSymbolAddress((void**)&nw,     g_nw);
    cudaGetSymbolAddress((void**)&degbuf, g_degbuf);
    cudaGetSymbolAddress((void**)&h,      g_h);
    cudaGetSymbolAddress((void**)&agg,    g_agg);
    cudaGetSymbolAddress((void**)&o1,     g_o1);
    cudaGetSymbolAddress((void**)&o2,     g_o2);

    float* out = (float*)d_out;
    const int TB = 256;
    int etot = e1 + e2 + e3;

    // launch 1: zero all degree buffers
    zero4_kernel<<<nblk((9 * NN + 3) / 4, TB), TB>>>((float4*)degbuf, (9 * NN) / 4);
    // launch 2: all weighted degree histograms
    deg_all_kernel<<<nblk(etot, TB), TB>>>(src1, dst1, w1, src2, dst2, w2, src3, dst3, w3,
                                           degbuf, e1, e2, e3);
    // launch 3: all edge norms + right-norm denominators
    nw_all_kernel<<<nblk(etot, TB), TB>>>(src1, dst1, w1, src2, dst2, w2, src3, dst3, w3,
                                          degbuf, nw, degbuf, e1, e2, e3);

    run_layer<F_IN,  F_HID>(x,  src1, dst1, nw,           degbuf + 2 * NN, W1, b1, o1,  h, agg, n, e1);
    run_layer<F_HID, F_OUT>(o1, src2, dst2, nw + e1,      degbuf + 5 * NN, W2, b2, o2,  h, agg, n, e2);
    run_layer<F_OUT, F_OUT>(o2, src3, dst3, nw + e1 + e2, degbuf + 8 * NN, W3, b3, out, h, agg, n, e3);
}

// round 16
// speedup vs baseline: 2.1294x; 1.1181x over previous
#include <cuda_runtime.h>
#include <cuda_bf16.h>

// ---------------------------------------------------------------------------
// 3-layer weighted GCN (DGL EdgeWeightNorm 'both' + GraphConv 'right')
// CSR gather-side aggregation: no feature atomics, no agg zeroing, fused finalize.
// ---------------------------------------------------------------------------

#define NN 100000
#define EE 1600000
#define F_IN  128
#define F_HID 64
#define F_OUT 32
#define NB_SCAN ((3 * NN + 255) / 256)     // 1172 scan blocks

static __device__ float g_degbuf[6 * NN];      // per layer: [outdeg NN | indeg NN]
static __device__ int   g_cnt[3 * NN];         // in-degree counts (concat layers)
static __device__ int   g_rp[3 * NN + 1];      // CSR row pointers (concat)
static __device__ int   g_bsum[2048];          // scan block sums
static __device__ int   g_cursor[3 * NN];      // fill cursors
static __device__ int   g_srcIdx[3 * EE];      // CSR payload: src node
static __device__ float g_wval[3 * EE];        // CSR payload: normalized weight
static __device__ float g_h[NN * F_HID];       // transformed features
static __device__ float g_o1[NN * F_HID];
static __device__ float g_o2[NN * F_OUT];

__device__ __forceinline__ float gcn_eps() { return 1e-12f; }

// ---------------- zero helpers ----------------
__global__ void zero4_kernel(float4* __restrict__ p, int n4) {
    int i = blockIdx.x * blockDim.x + threadIdx.x;
    if (i < n4) p[i] = make_float4(0.f, 0.f, 0.f, 0.f);
}
__global__ void zeroi_kernel(int* __restrict__ p, int n) {
    int i = blockIdx.x * blockDim.x + threadIdx.x;
    if (i < n) p[i] = 0;
}

// ---------------- weighted degree + count histograms, all 3 layers -------------------
__global__ void deg_cnt_all_kernel(
        const int* __restrict__ s1, const int* __restrict__ d1, const float* __restrict__ w1,
        const int* __restrict__ s2, const int* __restrict__ d2, const float* __restrict__ w2,
        const int* __restrict__ s3, const int* __restrict__ d3, const float* __restrict__ w3,
        float* __restrict__ degbuf, int* __restrict__ cnt, int e1, int e2, int e3) {
    int i = blockIdx.x * blockDim.x + threadIdx.x;
    if (i >= e1 + e2 + e3) return;
    const int* src; const int* dst; const float* w; int L, j;
    if (i < e1)            { j = i;           src = s1; dst = d1; w = w1; L = 0; }
    else if (i < e1 + e2)  { j = i - e1;      src = s2; dst = d2; w = w2; L = 1; }
    else                   { j = i - e1 - e2; src = s3; dst = d3; w = w3; L = 2; }
    float ww = w[j];
    int s = src[j], d = dst[j];
    float* base = degbuf + L * 2 * NN;
    atomicAdd(&base[s], ww);            // weighted out-degree
    atomicAdd(&base[NN + d], ww);       // weighted in-degree
    atomicAdd(&cnt[L * NN + d], 1);     // in-edge count
}

// ---------------- block-wise exclusive scan of cnt -> rp -----------------------------
__global__ void scan_blocks_kernel(const int* __restrict__ cnt, int* __restrict__ rp,
                                   int* __restrict__ bsum, int n) {
    __shared__ int sh[256];
    int t = threadIdx.x;
    int g = blockIdx.x * 256 + t;
    int v = (g < n) ? cnt[g] : 0;
    sh[t] = v;
    __syncthreads();
#pragma unroll
    for (int off = 1; off < 256; off <<= 1) {
        int a = (t >= off) ? sh[t - off] : 0;
        __syncthreads();
        sh[t] += a;
        __syncthreads();
    }
    if (g < n) rp[g] = sh[t] - v;                 // exclusive within block
    if (t == 255) bsum[blockIdx.x] = sh[255];     // block total
}

// single block: inclusive scan of block sums (nb <= 2048)
__global__ void scan_sums_kernel(int* __restrict__ bsum, int nb) {
    __shared__ int sh[2048];
    int t = threadIdx.x;                          // 1024 threads
    sh[t]        = (t < nb)        ? bsum[t]        : 0;
    sh[t + 1024] = (t + 1024 < nb) ? bsum[t + 1024] : 0;
    __syncthreads();
#pragma unroll
    for (int off = 1; off < 2048; off <<= 1) {
        int a = (t >= off)          ? sh[t - off]          : 0;
        int b = (t + 1024 >= off)   ? sh[t + 1024 - off]   : 0;
        __syncthreads();
        sh[t] += a;
        sh[t + 1024] += b;
        __syncthreads();
    }
    if (t < nb) bsum[t] = sh[t];
    if (t + 1024 < nb) bsum[t + 1024] = sh[t + 1024];
}

// add block offsets, zero cursors, cap rp
__global__ void scan_add_kernel(int* __restrict__ rp, const int* __restrict__ bsum,
                                int* __restrict__ cursor, int n, int etot) {
    int g = blockIdx.x * 256 + threadIdx.x;
    if (g < n) {
        int blk = blockIdx.x;
        int off = (blk == 0) ? 0 : bsum[blk - 1];
        rp[g] += off;
        cursor[g] = 0;
    }
    if (g == 0) rp[n] = etot;
}

// ---------------- edge norm + CSR fill, all 3 layers ---------------------------------
__global__ void fill_all_kernel(
        const int* __restrict__ s1, const int* __restrict__ d1, const float* __restrict__ w1,
        const int* __restrict__ s2, const int* __restrict__ d2, const float* __restrict__ w2,
        const int* __restrict__ s3, const int* __restrict__ d3, const float* __restrict__ w3,
        const float* __restrict__ degbuf, const int* __restrict__ rp, int* __restrict__ cursor,
        int* __restrict__ srcIdx, float* __restrict__ wval, int e1, int e2, int e3) {
    int i = blockIdx.x * blockDim.x + threadIdx.x;
    if (i >= e1 + e2 + e3) return;
    const int* src; const int* dst; const float* w; int L, j;
    if (i < e1)            { j = i;           src = s1; dst = d1; w = w1; L = 0; }
    else if (i < e1 + e2)  { j = i - e1;      src = s2; dst = d2; w = w2; L = 1; }
    else                   { j = i - e1 - e2; src = s3; dst = d3; w = w3; L = 2; }
    int s = src[j], d = dst[j];
    const float* base = degbuf + L * 2 * NN;
    float p = base[s] * base[NN + d];
    float v = w[j] * rsqrtf(fmaxf(p, gcn_eps()));
    int node = L * NN + d;
    int pos = rp[node] + atomicAdd(&cursor[node], 1);
    srcIdx[pos] = s;
    wval[pos] = v;
}

// ---------------- register-tiled GEMM: out[n,FOUT] = x[n,FIN] @ W[FIN,FOUT] ----------
template <int FIN, int FOUT>
__global__ void __launch_bounds__(256, 4)
gemm_kernel(const float* __restrict__ x, const float* __restrict__ Wg,
            float* __restrict__ out, int n) {
    constexpr int TM   = 128;
    constexpr int KC   = 16;
    constexpr int TMP  = TM + 4;
    constexpr int TPR  = FOUT / 4;
    constexpr int ROWG = 256 / TPR;
    constexpr int RPT  = TM / ROWG;
    constexpr int R4   = RPT / 4;
    constexpr int QP   = KC / 4;

    __shared__ float Ws[FIN * FOUT];
    __shared__ float XsT[KC][TMP];

    const int tid = threadIdx.x;
    for (int i = tid; i < FIN * FOUT / 4; i += 256)
        ((float4*)Ws)[i] = ((const float4*)Wg)[i];

    const int row0 = blockIdx.x * TM;
    const int r0   = (tid / TPR) * RPT;
    const int c0   = (tid % TPR) * 4;

    float acc[RPT][4];
#pragma unroll
    for (int i = 0; i < RPT; ++i)
#pragma unroll
        for (int j = 0; j < 4; ++j) acc[i][j] = 0.f;

    for (int kc = 0; kc < FIN; kc += KC) {
        __syncthreads();
#pragma unroll
        for (int i = tid; i < TM * QP; i += 256) {
            int r = i / QP, q = i - r * QP;
            float4 v = make_float4(0.f, 0.f, 0.f, 0.f);
            if (row0 + r < n)
                v = *(const float4*)(x + (size_t)(row0 + r) * FIN + kc + q * 4);
            XsT[q * 4 + 0][r] = v.x;
            XsT[q * 4 + 1][r] = v.y;
            XsT[q * 4 + 2][r] = v.z;
            XsT[q * 4 + 3][r] = v.w;
        }
        __syncthreads();

#pragma unroll
        for (int k = 0; k < KC; ++k) {
            float4 wv = *(const float4*)&Ws[(kc + k) * FOUT + c0];
            float4 xv4[R4];
#pragma unroll
            for (int u = 0; u < R4; ++u)
                xv4[u] = *(const float4*)&XsT[k][r0 + 4 * u];
            const float* xv = (const float*)xv4;
#pragma unroll
            for (int i = 0; i < RPT; ++i) {
                acc[i][0] = fmaf(xv[i], wv.x, acc[i][0]);
                acc[i][1] = fmaf(xv[i], wv.y, acc[i][1]);
                acc[i][2] = fmaf(xv[i], wv.z, acc[i][2]);
                acc[i][3] = fmaf(xv[i], wv.w, acc[i][3]);
            }
        }
    }

#pragma unroll
    for (int i = 0; i < RPT; ++i) {
        int row = row0 + r0 + i;
        if (row < n) {
            float4 o = make_float4(acc[i][0], acc[i][1], acc[i][2], acc[i][3]);
            *(float4*)(out + (size_t)row * FOUT + c0) = o;
        }
    }
}

// ---------------- CSR aggregation + normalize + bias (fused) -------------------------
// C4 = FOUT/4 threads per node; lane owns one float4 column chunk.
// out[node] = (sum_e wval[e] * h[srcIdx[e]]) / max(sum_e wval[e], eps) + b
template <int FOUT>
__global__ void csr_agg_kernel(const int* __restrict__ rp, const int* __restrict__ srcIdx,
                               const float* __restrict__ wval, const float* __restrict__ h,
                               const float* __restrict__ b, float* __restrict__ out,
                               int n, int base) {
    constexpr int C4 = FOUT / 4;
    int gid  = blockIdx.x * blockDim.x + threadIdx.x;
    int node = gid / C4;
    int lane = gid - node * C4;
    if (node >= n) return;

    int s0 = rp[base + node];
    int s1 = rp[base + node + 1];

    const float4* h4 = (const float4*)h;
    float4 acc = make_float4(0.f, 0.f, 0.f, 0.f);
    float ws = 0.f;
    for (int e = s0; e < s1; ++e) {
        int   s  = srcIdx[e];          // broadcast across C4 lanes
        float wv = wval[e];
        float4 hv = h4[(size_t)s * C4 + lane];
        acc.x = fmaf(wv, hv.x, acc.x);
        acc.y = fmaf(wv, hv.y, acc.y);
        acc.z = fmaf(wv, hv.z, acc.z);
        acc.w = fmaf(wv, hv.w, acc.w);
        ws += wv;
    }
    float inv = 1.f / fmaxf(ws, gcn_eps());
    float4 bb = ((const float4*)b)[lane];
    float4 o;
    o.x = acc.x * inv + bb.x;
    o.y = acc.y * inv + bb.y;
    o.z = acc.z * inv + bb.z;
    o.w = acc.w * inv + bb.w;
    ((float4*)out)[(size_t)node * C4 + lane] = o;
}

// ---------------------------------------------------------------------------

static inline int nblk(long long t, int tb) { return (int)((t + tb - 1) / tb); }

extern "C" void kernel_launch(void* const* d_in, const int* in_sizes, int n_in,
                              void* d_out, int out_size) {
    const float* x    = (const float*)d_in[0];
    const int*   src1 = (const int*)d_in[1];
    const int*   dst1 = (const int*)d_in[2];
    const float* w1   = (const float*)d_in[3];
    const int*   src2 = (const int*)d_in[4];
    const int*   dst2 = (const int*)d_in[5];
    const float* w2   = (const float*)d_in[6];
    const int*   src3 = (const int*)d_in[7];
    const int*   dst3 = (const int*)d_in[8];
    const float* w3   = (const float*)d_in[9];
    const float* W1   = (const float*)d_in[10];
    const float* b1   = (const float*)d_in[11];
    const float* W2   = (const float*)d_in[12];
    const float* b2   = (const float*)d_in[13];
    const float* W3   = (const float*)d_in[14];
    const float* b3   = (const float*)d_in[15];

    int n  = in_sizes[0] / F_IN;     // 100000
    int e1 = in_sizes[1];
    int e2 = in_sizes[4];
    int e3 = in_sizes[7];
    int etot = e1 + e2 + e3;

    float *degbuf, *wval, *h, *o1, *o2;
    int *cnt, *rp, *bsum, *cursor, *srcIdx;
    cudaGetSymbolAddress((void**)&degbuf, g_degbuf);
    cudaGetSymbolAddress((void**)&cnt,    g_cnt);
    cudaGetSymbolAddress((void**)&rp,     g_rp);
    cudaGetSymbolAddress((void**)&bsum,   g_bsum);
    cudaGetSymbolAddress((void**)&cursor, g_cursor);
    cudaGetSymbolAddress((void**)&srcIdx, g_srcIdx);
    cudaGetSymbolAddress((void**)&wval,   g_wval);
    cudaGetSymbolAddress((void**)&h,      g_h);
    cudaGetSymbolAddress((void**)&o1,     g_o1);
    cudaGetSymbolAddress((void**)&o2,     g_o2);

    float* out = (float*)d_out;
    const int TB = 256;

    // ---- build phase ----
    zero4_kernel<<<nblk((6 * NN) / 4, TB), TB>>>((float4*)degbuf, (6 * NN) / 4);
    zeroi_kernel<<<nblk(3 * NN, TB), TB>>>(cnt, 3 * NN);
    deg_cnt_all_kernel<<<nblk(etot, TB), TB>>>(src1, dst1, w1, src2, dst2, w2, src3, dst3, w3,
                                               degbuf, cnt, e1, e2, e3);
    scan_blocks_kernel<<<NB_SCAN, 256>>>(cnt, rp, bsum, 3 * NN);
    scan_sums_kernel<<<1, 1024>>>(bsum, NB_SCAN);
    scan_add_kernel<<<NB_SCAN, 256>>>(rp, bsum, cursor, 3 * NN, etot);
    fill_all_kernel<<<nblk(etot, TB), TB>>>(src1, dst1, w1, src2, dst2, w2, src3, dst3, w3,
                                            degbuf, rp, cursor, srcIdx, wval, e1, e2, e3);

    // ---- layer 1: 128 -> 64 ----
    gemm_kernel<F_IN, F_HID><<<nblk(n, 128), TB>>>(x, W1, h, n);
    csr_agg_kernel<F_HID><<<nblk((long long)n * (F_HID / 4), TB), TB>>>(rp, srcIdx, wval, h, b1, o1, n, 0);
    // ---- layer 2: 64 -> 32 ----
    gemm_kernel<F_HID, F_OUT><<<nblk(n, 128), TB>>>(o1, W2, h, n);
    csr_agg_kernel<F_OUT><<<nblk((long long)n * (F_OUT / 4), TB), TB>>>(rp, srcIdx, wval, h, b2, o2, n, NN);
    // ---- layer 3: 32 -> 32 ----
    gemm_kernel<F_OUT, F_OUT><<<nblk(n, 128), TB>>>(o2, W3, h, n);
    csr_agg_kernel<F_OUT><<<nblk((long long)n * (F_OUT / 4), TB), TB>>>(rp, srcIdx, wval, h, b3, out, n, 2 * NN);
}